// round 12
// baseline (speedup 1.0000x reference)
#include <cuda_runtime.h>
#include <cuda_fp16.h>
#include <cstdint>

#define N_NODES 100000
#define N_EDGES 1250000
#define DFEAT   64
#define UNITS   64

#define E4      (N_EDGES / 4)                          // 312500
#define SCAN_B  1024
#define VPT     8                                       // values per thread
#define SCAN_TILE (SCAN_B * VPT)                        // 8192
#define NB_SCAN ((N_NODES + SCAN_TILE - 1) / SCAN_TILE) // 13

#define FILLB   ((E4 + 255) / 256)                     // 1221 fill blocks
#define APPLYB  ((N_NODES * 8 + 255) / 256)            // 3125 apply blocks

// ---- scratch (device globals; allocation-free) ----
__device__ __half2 g_U[(size_t)N_NODES * (UNITS / 2)]; // T=F@W fp16, then scaled in-place
__device__ int     g_degi[N_NODES];
__device__ float   g_dinv[N_NODES];
__device__ int     g_rowptr[N_NODES + 1];
__device__ int     g_rank[N_EDGES];
__device__ int     g_col[N_EDGES];
__device__ int     g_is64;
// decoupled-lookback scan state
__device__ int     g_agg[NB_SCAN];
__device__ int     g_inc[NB_SCAN];
__device__ int     g_flag[NB_SCAN];   // 0=none, 1=aggregate, 2=inclusive

// f32x2 packed FMA helpers (Blackwell FFMA2)
#define FMA_F32X2(acc, a, b) \
    asm("fma.rn.f32x2 %0, %1, %2, %0;" : "+l"(acc) : "l"(a), "l"(b))
#define PACK_DUP_F32X2(out, s) \
    asm("mov.b64 %0, {%1, %1};" : "=l"(out) : "r"(s))

__device__ __forceinline__ void load_edges4(const void* __restrict__ ei,
                                            int t, size_t elem_off, int v[4], int is64) {
    if (is64) {
        const longlong2* p = (const longlong2*)((const long long*)ei + elem_off);
        longlong2 a = p[t * 2];
        longlong2 b = p[t * 2 + 1];
        v[0] = (int)a.x; v[1] = (int)a.y; v[2] = (int)b.x; v[3] = (int)b.y;
    } else {
        int4 a = ((const int4*)((const int*)ei + elem_off))[t];
        v[0] = a.x; v[1] = a.y; v[2] = a.z; v[3] = a.w;
    }
}

// ---------------------------------------------------------------------------
// K1 (stream 0): zero degree counters + scan flags + dtype detect
// ---------------------------------------------------------------------------
__global__ void k_zero_detect(const void* __restrict__ ei) {
    int i = blockIdx.x * blockDim.x + threadIdx.x;
    int stride = gridDim.x * blockDim.x;
    for (int j = i; j < N_NODES; j += stride) g_degi[j] = 0;
    if (i < NB_SCAN) { g_flag[i] = 0; g_agg[i] = 0; g_inc[i] = 0; }

    if (blockIdx.x == 0 && threadIdx.x < 32) {
        const long long* p = (const long long*)ei;
        int bad = 0;
#pragma unroll
        for (int k = 0; k < 8; k++) {
            long long v = p[threadIdx.x * 8 + k];
            bad |= (v < 0 || v >= N_NODES);
        }
        unsigned any = __ballot_sync(0xFFFFFFFFu, bad);
        if (threadIdx.x == 0) g_is64 = (any == 0u) ? 1 : 0;
    }
}

// ---------------------------------------------------------------------------
// K2 (stream 0): degree count + rank capture
// ---------------------------------------------------------------------------
__global__ void k_degree_rank(const void* __restrict__ ei) {
    int t = blockIdx.x * blockDim.x + threadIdx.x;
    if (t >= E4) return;
    int r[4];
    load_edges4(ei, t, 0, r, g_is64);
    int4 rk;
    rk.x = atomicAdd(&g_degi[r[0]], 1);
    rk.y = atomicAdd(&g_degi[r[1]], 1);
    rk.z = atomicAdd(&g_degi[r[2]], 1);
    rk.w = atomicAdd(&g_degi[r[3]], 1);
    reinterpret_cast<int4*>(g_rank)[t] = rk;
}

// ---------------------------------------------------------------------------
// K3 (stream 0): scan — 8 elems/thread, shfl warp scans, warp-parallel
//                windowed lookback (13 blocks => single window)
// ---------------------------------------------------------------------------
__global__ void __launch_bounds__(SCAN_B)
k_scan() {
    __shared__ int s_warp[32];
    __shared__ int s_prefix;

    const int tid  = threadIdx.x;
    const int bid  = blockIdx.x;
    const int lane = tid & 31;
    const int wid  = tid >> 5;
    const unsigned FULL = 0xFFFFFFFFu;

    int base = (bid * SCAN_B + tid) * VPT;
    int d[VPT];
    int tsum = 0;
    bool active = (base < N_NODES);   // N_NODES % VPT == 0 -> all-or-nothing
    if (active) {
        int4 a = *reinterpret_cast<const int4*>(&g_degi[base]);
        int4 b = *reinterpret_cast<const int4*>(&g_degi[base + 4]);
        d[0] = a.x; d[1] = a.y; d[2] = a.z; d[3] = a.w;
        d[4] = b.x; d[5] = b.y; d[6] = b.z; d[7] = b.w;
#pragma unroll
        for (int k = 0; k < VPT; k++) tsum += d[k];
    } else {
#pragma unroll
        for (int k = 0; k < VPT; k++) d[k] = 0;
    }

    // warp inclusive scan of per-thread sums
    int x = tsum;
#pragma unroll
    for (int o = 1; o < 32; o <<= 1) {
        int t = __shfl_up_sync(FULL, x, o);
        if (lane >= o) x += t;
    }
    if (lane == 31) s_warp[wid] = x;
    __syncthreads();

    // warp 0 scans the 32 warp totals
    if (wid == 0) {
        int w = s_warp[lane];
        int y = w;
#pragma unroll
        for (int o = 1; o < 32; o <<= 1) {
            int t = __shfl_up_sync(FULL, y, o);
            if (lane >= o) y += t;
        }
        s_warp[lane] = y - w;   // exclusive warp prefix
    }
    __syncthreads();

    int block_excl  = s_warp[wid] + (x - tsum);   // this thread's exclusive offset in block
    int block_total;
    if (tid == SCAN_B - 1) s_prefix = block_excl + tsum;  // reuse as total holder
    __syncthreads();
    block_total = s_prefix;
    __syncthreads();

    // publish aggregate, then warp-parallel lookback (warp 0)
    if (tid == 0 && bid > 0) {
        atomicExch(&g_agg[bid], block_total);
        __threadfence();
        atomicExch(&g_flag[bid], 1);
    }
    if (wid == 0) {
        int prefix = 0;
        if (bid > 0) {
            int p = bid - 1;
            while (true) {
                int idx = p - lane;
                int f = 2, v = 0;
                if (idx >= 0) {
                    while ((f = atomicAdd(&g_flag[idx], 0)) == 0) __nanosleep(32);
                    v = (f == 2) ? atomicAdd(&g_inc[idx], 0)
                                 : atomicAdd(&g_agg[idx], 0);
                }
                unsigned m2 = __ballot_sync(FULL, f == 2);
                int first = __ffs(m2) - 1;            // nearest inclusive predecessor
                int take  = (first >= 0) ? first : 31;
                int val = (lane <= take) ? v : 0;
#pragma unroll
                for (int o = 16; o > 0; o >>= 1) val += __shfl_down_sync(FULL, val, o);
                val = __shfl_sync(FULL, val, 0);
                prefix += val;
                if (first >= 0) break;
                p -= 32;
            }
        }
        if (lane == 0) {
            atomicExch(&g_inc[bid], prefix + block_total);
            __threadfence();
            atomicExch(&g_flag[bid], 2);
            s_prefix = prefix;
        }
    }
    __syncthreads();
    int gpre = s_prefix;

    if (active) {
        int run = gpre + block_excl;
        int4 rp0, rp1;
        float4 dv0, dv1;
        int e0 = run;              rp0.x = e0;
        int e1 = e0 + d[0];        rp0.y = e1;
        int e2 = e1 + d[1];        rp0.z = e2;
        int e3 = e2 + d[2];        rp0.w = e3;
        int e4 = e3 + d[3];        rp1.x = e4;
        int e5 = e4 + d[4];        rp1.y = e5;
        int e6 = e5 + d[5];        rp1.z = e6;
        int e7 = e6 + d[6];        rp1.w = e7;
        dv0.x = (d[0] > 0) ? rsqrtf((float)d[0]) : 0.f;
        dv0.y = (d[1] > 0) ? rsqrtf((float)d[1]) : 0.f;
        dv0.z = (d[2] > 0) ? rsqrtf((float)d[2]) : 0.f;
        dv0.w = (d[3] > 0) ? rsqrtf((float)d[3]) : 0.f;
        dv1.x = (d[4] > 0) ? rsqrtf((float)d[4]) : 0.f;
        dv1.y = (d[5] > 0) ? rsqrtf((float)d[5]) : 0.f;
        dv1.z = (d[6] > 0) ? rsqrtf((float)d[6]) : 0.f;
        dv1.w = (d[7] > 0) ? rsqrtf((float)d[7]) : 0.f;
        *reinterpret_cast<int4*>(&g_rowptr[base])     = rp0;
        *reinterpret_cast<int4*>(&g_rowptr[base + 4]) = rp1;
        *reinterpret_cast<float4*>(&g_dinv[base])     = dv0;
        *reinterpret_cast<float4*>(&g_dinv[base + 4]) = dv1;
    }
    if (tid == 0 && bid == 0) g_rowptr[N_NODES] = N_EDGES;
}

// ---------------------------------------------------------------------------
// K4 (stream 2, overlapped): T = fp16(F @ W)  — no dinv; scaled later
// ---------------------------------------------------------------------------
__global__ void k_transform(const float* __restrict__ F,
                            const float* __restrict__ W) {
    __shared__ float4 Ws[DFEAT * (UNITS / 4)];  // 16 KB
    for (int i = threadIdx.x; i < DFEAT * (UNITS / 4); i += blockDim.x)
        Ws[i] = reinterpret_cast<const float4*>(W)[i];
    __syncthreads();

    int node = blockIdx.x * blockDim.x + threadIdx.x;
    if (node >= N_NODES) return;

    unsigned long long acc[32];
#pragma unroll
    for (int j = 0; j < 32; j++) acc[j] = 0ull;

    const float4* Frow = reinterpret_cast<const float4*>(F + (size_t)node * DFEAT);
#pragma unroll 4
    for (int k4 = 0; k4 < 16; k4++) {
        float4 f = Frow[k4];
        float fv[4] = {f.x, f.y, f.z, f.w};
#pragma unroll
        for (int kk = 0; kk < 4; kk++) {
            unsigned long long p2;
            PACK_DUP_F32X2(p2, __float_as_uint(fv[kk]));
            const unsigned long long* wrow =
                reinterpret_cast<const unsigned long long*>(&Ws[(k4 * 4 + kk) * 16]);
#pragma unroll
            for (int j = 0; j < 32; j++) FMA_F32X2(acc[j], p2, wrow[j]);
        }
    }
    uint4* Urow = reinterpret_cast<uint4*>(&g_U[(size_t)node * 32]);
#pragma unroll
    for (int q = 0; q < 8; q++) {
        uint4 o;
        float2 p0 = *reinterpret_cast<float2*>(&acc[4 * q]);
        float2 p1 = *reinterpret_cast<float2*>(&acc[4 * q + 1]);
        float2 p2f = *reinterpret_cast<float2*>(&acc[4 * q + 2]);
        float2 p3 = *reinterpret_cast<float2*>(&acc[4 * q + 3]);
        __half2 h0 = __floats2half2_rn(p0.x, p0.y);
        __half2 h1 = __floats2half2_rn(p1.x, p1.y);
        __half2 h2 = __floats2half2_rn(p2f.x, p2f.y);
        __half2 h3 = __floats2half2_rn(p3.x, p3.y);
        o.x = *reinterpret_cast<unsigned*>(&h0);
        o.y = *reinterpret_cast<unsigned*>(&h1);
        o.z = *reinterpret_cast<unsigned*>(&h2);
        o.w = *reinterpret_cast<unsigned*>(&h3);
        Urow[q] = o;
    }
}

// ---------------------------------------------------------------------------
// K5 (stream 0, after join): CSR fill by rank ∥ in-place U *= dinv[node]
// ---------------------------------------------------------------------------
__global__ void k_fillapply(const void* __restrict__ ei) {
    int tid = threadIdx.x;
    if (blockIdx.x < FILLB) {
        int t = blockIdx.x * 256 + tid;
        if (t >= E4) return;
        const int is64 = g_is64;
        int r[4], c[4];
        load_edges4(ei, t, 0, r, is64);
        load_edges4(ei, t, N_EDGES, c, is64);
        int4 rk = reinterpret_cast<const int4*>(g_rank)[t];
        g_col[g_rowptr[r[0]] + rk.x] = c[0];
        g_col[g_rowptr[r[1]] + rk.y] = c[1];
        g_col[g_rowptr[r[2]] + rk.z] = c[2];
        g_col[g_rowptr[r[3]] + rk.w] = c[3];
    } else {
        int idx = (blockIdx.x - FILLB) * 256 + tid;   // uint4 index, 8 per node
        if (idx >= N_NODES * 8) return;
        int node = idx >> 3;
        float dv = g_dinv[node];
        uint4* p = reinterpret_cast<uint4*>(g_U) + idx;
        uint4 u = *p;
        float2 f;
        __half2 h;
        f = __half22float2(*(__half2*)&u.x); h = __floats2half2_rn(f.x * dv, f.y * dv); u.x = *(unsigned*)&h;
        f = __half22float2(*(__half2*)&u.y); h = __floats2half2_rn(f.x * dv, f.y * dv); u.y = *(unsigned*)&h;
        f = __half22float2(*(__half2*)&u.z); h = __floats2half2_rn(f.x * dv, f.y * dv); u.z = *(unsigned*)&h;
        f = __half22float2(*(__half2*)&u.w); h = __floats2half2_rn(f.x * dv, f.y * dv); u.w = *(unsigned*)&h;
        *p = u;
    }
}

// ---------------------------------------------------------------------------
// K6 (stream 0): gather + epilogue. 8 threads/node, fp32 accumulation.
// ---------------------------------------------------------------------------
__global__ void k_gather(float4* __restrict__ out4,
                         const float* __restrict__ bias) {
    int gid = blockIdx.x * blockDim.x + threadIdx.x;
    int node = gid >> 3;
    int h = gid & 7;
    if (node >= N_NODES) return;

    const uint4* Ub = reinterpret_cast<const uint4*>(g_U);
    int start = g_rowptr[node];
    int end   = g_rowptr[node + 1];

    float2 a0 = make_float2(0.f, 0.f), a1 = a0, a2 = a0, a3 = a0;
    float2 b0 = a0, b1 = a0, b2 = a0, b3 = a0;

    int j = start;
    for (; j + 1 < end; j += 2) {
        int i0 = g_col[j];
        int i1 = g_col[j + 1];
        uint4 u = Ub[i0 * 8 + h];
        uint4 v = Ub[i1 * 8 + h];
        float2 f;
        f = __half22float2(*(__half2*)&u.x); a0.x += f.x; a0.y += f.y;
        f = __half22float2(*(__half2*)&u.y); a1.x += f.x; a1.y += f.y;
        f = __half22float2(*(__half2*)&u.z); a2.x += f.x; a2.y += f.y;
        f = __half22float2(*(__half2*)&u.w); a3.x += f.x; a3.y += f.y;
        f = __half22float2(*(__half2*)&v.x); b0.x += f.x; b0.y += f.y;
        f = __half22float2(*(__half2*)&v.y); b1.x += f.x; b1.y += f.y;
        f = __half22float2(*(__half2*)&v.z); b2.x += f.x; b2.y += f.y;
        f = __half22float2(*(__half2*)&v.w); b3.x += f.x; b3.y += f.y;
    }
    if (j < end) {
        uint4 u = Ub[g_col[j] * 8 + h];
        float2 f;
        f = __half22float2(*(__half2*)&u.x); a0.x += f.x; a0.y += f.y;
        f = __half22float2(*(__half2*)&u.y); a1.x += f.x; a1.y += f.y;
        f = __half22float2(*(__half2*)&u.z); a2.x += f.x; a2.y += f.y;
        f = __half22float2(*(__half2*)&u.w); a3.x += f.x; a3.y += f.y;
    }
    a0.x += b0.x; a0.y += b0.y;  a1.x += b1.x; a1.y += b1.y;
    a2.x += b2.x; a2.y += b2.y;  a3.x += b3.x; a3.y += b3.y;

    float dv = g_dinv[node];
    float4 bb0 = reinterpret_cast<const float4*>(bias)[h * 2];
    float4 bb1 = reinterpret_cast<const float4*>(bias)[h * 2 + 1];
    float4 v0, v1;
    v0.x = fmaxf(fmaf(dv, a0.x, bb0.x), 0.f);
    v0.y = fmaxf(fmaf(dv, a0.y, bb0.y), 0.f);
    v0.z = fmaxf(fmaf(dv, a1.x, bb0.z), 0.f);
    v0.w = fmaxf(fmaf(dv, a1.y, bb0.w), 0.f);
    v1.x = fmaxf(fmaf(dv, a2.x, bb1.x), 0.f);
    v1.y = fmaxf(fmaf(dv, a2.y, bb1.y), 0.f);
    v1.z = fmaxf(fmaf(dv, a3.x, bb1.z), 0.f);
    v1.w = fmaxf(fmaf(dv, a3.y, bb1.w), 0.f);
    out4[node * 16 + h * 2]     = v0;
    out4[node * 16 + h * 2 + 1] = v1;
}

// ---------------------------------------------------------------------------
// Side stream + events (host objects, static init — no device allocations)
// ---------------------------------------------------------------------------
static cudaStream_t g_s2;
static cudaEvent_t  g_evA, g_evB;
static struct SideStreamInit {
    SideStreamInit() {
        cudaStreamCreateWithFlags(&g_s2, cudaStreamNonBlocking);
        cudaEventCreateWithFlags(&g_evA, cudaEventDisableTiming);
        cudaEventCreateWithFlags(&g_evB, cudaEventDisableTiming);
    }
} g_side_init;

// ---------------------------------------------------------------------------
extern "C" void kernel_launch(void* const* d_in, const int* in_sizes, int n_in,
                              void* d_out, int out_size) {
    const float* features = (const float*)d_in[0];       // [N, 64]
    const void*  edge_idx = d_in[1];                     // [2, E] int32 or int64
    const float* weight   = (const float*)d_in[2];       // [64, 64]
    const float* bias     = (const float*)d_in[3];       // [64]
    float4*      out4     = (float4*)d_out;              // [N, 64] fp32

    const int B = 256;
    cudaStream_t s0 = 0;

    // fork: transform (independent of edges) runs on side stream
    cudaEventRecord(g_evA, s0);
    cudaStreamWaitEvent(g_s2, g_evA, 0);
    k_transform<<<(N_NODES + B - 1) / B, B, 0, g_s2>>>(features, weight);
    cudaEventRecord(g_evB, g_s2);

    // main chain on stream 0
    k_zero_detect<<<512, B>>>(edge_idx);
    k_degree_rank<<<(E4 + B - 1) / B, B>>>(edge_idx);
    k_scan<<<NB_SCAN, SCAN_B>>>();

    // join: fill needs rowptr (s0); applydinv needs dinv (s0) + T (s2)
    cudaStreamWaitEvent(s0, g_evB, 0);
    k_fillapply<<<FILLB + APPLYB, B>>>(edge_idx);
    k_gather<<<(N_NODES * 8 + B - 1) / B, B>>>(out4, bias);
}

// round 13
// speedup vs baseline: 1.4513x; 1.4513x over previous
#include <cuda_runtime.h>
#include <cuda_fp16.h>
#include <cstdint>

#define N_NODES 100000
#define N_EDGES 1250000
#define DFEAT   64
#define UNITS   64

#define E4      (N_EDGES / 4)                          // 312500
#define SCAN_B  1024
#define VPT     8
#define SCAN_TILE (SCAN_B * VPT)                        // 8192
#define NB_SCAN ((N_NODES + SCAN_TILE - 1) / SCAN_TILE) // 13

#define FILLB   ((E4 + 255) / 256)                     // 1221 fill blocks
#define APPLYB  ((N_NODES * 8 + 255) / 256)            // 3125 apply blocks

// ---- scratch (device globals; allocation-free, zero-initialized) ----
__device__ __half2 g_U[(size_t)N_NODES * (UNITS / 2)]; // T=F@W fp16, scaled in-place
__device__ int     g_degi[N_NODES];                    // zeroed by gather tail each launch
__device__ float   g_dinv[N_NODES];
__device__ int     g_rowptr[N_NODES + 1];
__device__ int     g_rank[N_EDGES];
__device__ int     g_col[N_EDGES];
// decoupled-lookback scan state (flags zeroed by gather tail each launch)
__device__ int     g_agg[NB_SCAN];
__device__ int     g_inc[NB_SCAN];
__device__ int     g_flag[NB_SCAN];

// f32x2 packed FMA helpers (Blackwell FFMA2)
#define FMA_F32X2(acc, a, b) \
    asm("fma.rn.f32x2 %0, %1, %2, %0;" : "+l"(acc) : "l"(a), "l"(b))
#define PACK_DUP_F32X2(out, s) \
    asm("mov.b64 %0, {%1, %1};" : "=l"(out) : "r"(s))

// per-block dtype detect: int32 data read as int64 pairs two random indices,
// which lands outside [0, N_NODES) with overwhelming probability per value.
__device__ __forceinline__ int block_detect_is64(const void* __restrict__ ei,
                                                 int* s_flag) {
    if (threadIdx.x == 0) {
        const long long* p = (const long long*)ei;
        int ok = 1;
#pragma unroll
        for (int k = 0; k < 8; k++) {
            long long v = p[k];
            ok &= (v >= 0 && v < N_NODES);
        }
        *s_flag = ok;
    }
    __syncthreads();
    return *s_flag;
}

__device__ __forceinline__ void load_edges4(const void* __restrict__ ei,
                                            int t, size_t elem_off, int v[4], int is64) {
    if (is64) {
        const longlong2* p = (const longlong2*)((const long long*)ei + elem_off);
        longlong2 a = p[t * 2];
        longlong2 b = p[t * 2 + 1];
        v[0] = (int)a.x; v[1] = (int)a.y; v[2] = (int)b.x; v[3] = (int)b.y;
    } else {
        int4 a = ((const int4*)((const int*)ei + elem_off))[t];
        v[0] = a.x; v[1] = a.y; v[2] = a.z; v[3] = a.w;
    }
}

// ---------------------------------------------------------------------------
// K1 (stream 0): degree count + rank capture (counters pre-zeroed by the
//                previous launch's gather tail / static init)
// ---------------------------------------------------------------------------
__global__ void k_degree_rank(const void* __restrict__ ei) {
    __shared__ int s_is64;
    int is64 = block_detect_is64(ei, &s_is64);
    int t = blockIdx.x * blockDim.x + threadIdx.x;
    if (t >= E4) return;
    int r[4];
    load_edges4(ei, t, 0, r, is64);
    int4 rk;
    rk.x = atomicAdd(&g_degi[r[0]], 1);
    rk.y = atomicAdd(&g_degi[r[1]], 1);
    rk.z = atomicAdd(&g_degi[r[2]], 1);
    rk.w = atomicAdd(&g_degi[r[3]], 1);
    reinterpret_cast<int4*>(g_rank)[t] = rk;
}

// ---------------------------------------------------------------------------
// K2 (stream 0): scan — 8 elems/thread, shfl warp scans, warp-parallel
//                windowed lookback (13 blocks => single window)
// ---------------------------------------------------------------------------
__global__ void __launch_bounds__(SCAN_B)
k_scan() {
    __shared__ int s_warp[32];
    __shared__ int s_prefix;

    const int tid  = threadIdx.x;
    const int bid  = blockIdx.x;
    const int lane = tid & 31;
    const int wid  = tid >> 5;
    const unsigned FULL = 0xFFFFFFFFu;

    int base = (bid * SCAN_B + tid) * VPT;
    int d[VPT];
    int tsum = 0;
    bool active = (base < N_NODES);   // N_NODES % VPT == 0 -> all-or-nothing
    if (active) {
        int4 a = *reinterpret_cast<const int4*>(&g_degi[base]);
        int4 b = *reinterpret_cast<const int4*>(&g_degi[base + 4]);
        d[0] = a.x; d[1] = a.y; d[2] = a.z; d[3] = a.w;
        d[4] = b.x; d[5] = b.y; d[6] = b.z; d[7] = b.w;
#pragma unroll
        for (int k = 0; k < VPT; k++) tsum += d[k];
    } else {
#pragma unroll
        for (int k = 0; k < VPT; k++) d[k] = 0;
    }

    int x = tsum;
#pragma unroll
    for (int o = 1; o < 32; o <<= 1) {
        int t = __shfl_up_sync(FULL, x, o);
        if (lane >= o) x += t;
    }
    if (lane == 31) s_warp[wid] = x;
    __syncthreads();

    if (wid == 0) {
        int w = s_warp[lane];
        int y = w;
#pragma unroll
        for (int o = 1; o < 32; o <<= 1) {
            int t = __shfl_up_sync(FULL, y, o);
            if (lane >= o) y += t;
        }
        s_warp[lane] = y - w;
    }
    __syncthreads();

    int block_excl = s_warp[wid] + (x - tsum);
    int block_total;
    if (tid == SCAN_B - 1) s_prefix = block_excl + tsum;
    __syncthreads();
    block_total = s_prefix;
    __syncthreads();

    if (tid == 0 && bid > 0) {
        atomicExch(&g_agg[bid], block_total);
        __threadfence();
        atomicExch(&g_flag[bid], 1);
    }
    if (wid == 0) {
        int prefix = 0;
        if (bid > 0) {
            int p = bid - 1;
            while (true) {
                int idx = p - lane;
                int f = 2, v = 0;
                if (idx >= 0) {
                    while ((f = atomicAdd(&g_flag[idx], 0)) == 0) __nanosleep(32);
                    v = (f == 2) ? atomicAdd(&g_inc[idx], 0)
                                 : atomicAdd(&g_agg[idx], 0);
                }
                unsigned m2 = __ballot_sync(FULL, f == 2);
                int first = __ffs(m2) - 1;
                int take  = (first >= 0) ? first : 31;
                int val = (lane <= take) ? v : 0;
#pragma unroll
                for (int o = 16; o > 0; o >>= 1) val += __shfl_down_sync(FULL, val, o);
                val = __shfl_sync(FULL, val, 0);
                prefix += val;
                if (first >= 0) break;
                p -= 32;
            }
        }
        if (lane == 0) {
            atomicExch(&g_inc[bid], prefix + block_total);
            __threadfence();
            atomicExch(&g_flag[bid], 2);
            s_prefix = prefix;
        }
    }
    __syncthreads();
    int gpre = s_prefix;

    if (active) {
        int run = gpre + block_excl;
        int4 rp0, rp1;
        float4 dv0, dv1;
        int e0 = run;              rp0.x = e0;
        int e1 = e0 + d[0];        rp0.y = e1;
        int e2 = e1 + d[1];        rp0.z = e2;
        int e3 = e2 + d[2];        rp0.w = e3;
        int e4 = e3 + d[3];        rp1.x = e4;
        int e5 = e4 + d[4];        rp1.y = e5;
        int e6 = e5 + d[5];        rp1.z = e6;
        int e7 = e6 + d[6];        rp1.w = e7;
        dv0.x = (d[0] > 0) ? rsqrtf((float)d[0]) : 0.f;
        dv0.y = (d[1] > 0) ? rsqrtf((float)d[1]) : 0.f;
        dv0.z = (d[2] > 0) ? rsqrtf((float)d[2]) : 0.f;
        dv0.w = (d[3] > 0) ? rsqrtf((float)d[3]) : 0.f;
        dv1.x = (d[4] > 0) ? rsqrtf((float)d[4]) : 0.f;
        dv1.y = (d[5] > 0) ? rsqrtf((float)d[5]) : 0.f;
        dv1.z = (d[6] > 0) ? rsqrtf((float)d[6]) : 0.f;
        dv1.w = (d[7] > 0) ? rsqrtf((float)d[7]) : 0.f;
        *reinterpret_cast<int4*>(&g_rowptr[base])     = rp0;
        *reinterpret_cast<int4*>(&g_rowptr[base + 4]) = rp1;
        *reinterpret_cast<float4*>(&g_dinv[base])     = dv0;
        *reinterpret_cast<float4*>(&g_dinv[base + 4]) = dv1;
    }
    if (tid == 0 && bid == 0) g_rowptr[N_NODES] = N_EDGES;
}

// ---------------------------------------------------------------------------
// K3 (stream 2, overlapped): T = fp16(F @ W)  — no dinv; scaled later
// ---------------------------------------------------------------------------
__global__ void k_transform(const float* __restrict__ F,
                            const float* __restrict__ W) {
    __shared__ float4 Ws[DFEAT * (UNITS / 4)];  // 16 KB
    for (int i = threadIdx.x; i < DFEAT * (UNITS / 4); i += blockDim.x)
        Ws[i] = reinterpret_cast<const float4*>(W)[i];
    __syncthreads();

    int node = blockIdx.x * blockDim.x + threadIdx.x;
    if (node >= N_NODES) return;

    unsigned long long acc[32];
#pragma unroll
    for (int j = 0; j < 32; j++) acc[j] = 0ull;

    const float4* Frow = reinterpret_cast<const float4*>(F + (size_t)node * DFEAT);
#pragma unroll 4
    for (int k4 = 0; k4 < 16; k4++) {
        float4 f = Frow[k4];
        float fv[4] = {f.x, f.y, f.z, f.w};
#pragma unroll
        for (int kk = 0; kk < 4; kk++) {
            unsigned long long p2;
            PACK_DUP_F32X2(p2, __float_as_uint(fv[kk]));
            const unsigned long long* wrow =
                reinterpret_cast<const unsigned long long*>(&Ws[(k4 * 4 + kk) * 16]);
#pragma unroll
            for (int j = 0; j < 32; j++) FMA_F32X2(acc[j], p2, wrow[j]);
        }
    }
    uint4* Urow = reinterpret_cast<uint4*>(&g_U[(size_t)node * 32]);
#pragma unroll
    for (int q = 0; q < 8; q++) {
        uint4 o;
        float2 p0 = *reinterpret_cast<float2*>(&acc[4 * q]);
        float2 p1 = *reinterpret_cast<float2*>(&acc[4 * q + 1]);
        float2 p2f = *reinterpret_cast<float2*>(&acc[4 * q + 2]);
        float2 p3 = *reinterpret_cast<float2*>(&acc[4 * q + 3]);
        __half2 h0 = __floats2half2_rn(p0.x, p0.y);
        __half2 h1 = __floats2half2_rn(p1.x, p1.y);
        __half2 h2 = __floats2half2_rn(p2f.x, p2f.y);
        __half2 h3 = __floats2half2_rn(p3.x, p3.y);
        o.x = *reinterpret_cast<unsigned*>(&h0);
        o.y = *reinterpret_cast<unsigned*>(&h1);
        o.z = *reinterpret_cast<unsigned*>(&h2);
        o.w = *reinterpret_cast<unsigned*>(&h3);
        Urow[q] = o;
    }
}

// ---------------------------------------------------------------------------
// K4 (stream 0, after join): CSR fill by rank ∥ in-place U *= dinv[node]
// ---------------------------------------------------------------------------
__global__ void k_fillapply(const void* __restrict__ ei) {
    int tid = threadIdx.x;
    if (blockIdx.x < FILLB) {
        __shared__ int s_is64;
        int is64 = block_detect_is64(ei, &s_is64);
        int t = blockIdx.x * 256 + tid;
        if (t >= E4) return;
        int r[4], c[4];
        load_edges4(ei, t, 0, r, is64);
        load_edges4(ei, t, N_EDGES, c, is64);
        int4 rk = reinterpret_cast<const int4*>(g_rank)[t];
        g_col[g_rowptr[r[0]] + rk.x] = c[0];
        g_col[g_rowptr[r[1]] + rk.y] = c[1];
        g_col[g_rowptr[r[2]] + rk.z] = c[2];
        g_col[g_rowptr[r[3]] + rk.w] = c[3];
    } else {
        int idx = (blockIdx.x - FILLB) * 256 + tid;   // uint4 index, 8 per node
        if (idx >= N_NODES * 8) return;
        int node = idx >> 3;
        float dv = g_dinv[node];
        uint4* p = reinterpret_cast<uint4*>(g_U) + idx;
        uint4 u = *p;
        float2 f;
        __half2 h;
        f = __half22float2(*(__half2*)&u.x); h = __floats2half2_rn(f.x * dv, f.y * dv); u.x = *(unsigned*)&h;
        f = __half22float2(*(__half2*)&u.y); h = __floats2half2_rn(f.x * dv, f.y * dv); u.y = *(unsigned*)&h;
        f = __half22float2(*(__half2*)&u.z); h = __floats2half2_rn(f.x * dv, f.y * dv); u.z = *(unsigned*)&h;
        f = __half22float2(*(__half2*)&u.w); h = __floats2half2_rn(f.x * dv, f.y * dv); u.w = *(unsigned*)&h;
        *p = u;
    }
}

// ---------------------------------------------------------------------------
// K5 (stream 0): gather + epilogue + self-restoring state reset.
//     8 threads/node, fp32 accumulation, no atomics.
// ---------------------------------------------------------------------------
__global__ void k_gather(float4* __restrict__ out4,
                         const float* __restrict__ bias) {
    int gid = blockIdx.x * blockDim.x + threadIdx.x;
    int node = gid >> 3;    // grid is exactly N_NODES*8 threads
    int h = gid & 7;

    const uint4* Ub = reinterpret_cast<const uint4*>(g_U);
    int start = g_rowptr[node];
    int end   = g_rowptr[node + 1];

    float2 a0 = make_float2(0.f, 0.f), a1 = a0, a2 = a0, a3 = a0;
    float2 b0 = a0, b1 = a0, b2 = a0, b3 = a0;

    int j = start;
    for (; j + 1 < end; j += 2) {
        int i0 = g_col[j];
        int i1 = g_col[j + 1];
        uint4 u = Ub[i0 * 8 + h];
        uint4 v = Ub[i1 * 8 + h];
        float2 f;
        f = __half22float2(*(__half2*)&u.x); a0.x += f.x; a0.y += f.y;
        f = __half22float2(*(__half2*)&u.y); a1.x += f.x; a1.y += f.y;
        f = __half22float2(*(__half2*)&u.z); a2.x += f.x; a2.y += f.y;
        f = __half22float2(*(__half2*)&u.w); a3.x += f.x; a3.y += f.y;
        f = __half22float2(*(__half2*)&v.x); b0.x += f.x; b0.y += f.y;
        f = __half22float2(*(__half2*)&v.y); b1.x += f.x; b1.y += f.y;
        f = __half22float2(*(__half2*)&v.z); b2.x += f.x; b2.y += f.y;
        f = __half22float2(*(__half2*)&v.w); b3.x += f.x; b3.y += f.y;
    }
    if (j < end) {
        uint4 u = Ub[g_col[j] * 8 + h];
        float2 f;
        f = __half22float2(*(__half2*)&u.x); a0.x += f.x; a0.y += f.y;
        f = __half22float2(*(__half2*)&u.y); a1.x += f.x; a1.y += f.y;
        f = __half22float2(*(__half2*)&u.z); a2.x += f.x; a2.y += f.y;
        f = __half22float2(*(__half2*)&u.w); a3.x += f.x; a3.y += f.y;
    }
    a0.x += b0.x; a0.y += b0.y;  a1.x += b1.x; a1.y += b1.y;
    a2.x += b2.x; a2.y += b2.y;  a3.x += b3.x; a3.y += b3.y;

    float dv = g_dinv[node];
    float4 bb0 = reinterpret_cast<const float4*>(bias)[h * 2];
    float4 bb1 = reinterpret_cast<const float4*>(bias)[h * 2 + 1];
    float4 v0, v1;
    v0.x = fmaxf(fmaf(dv, a0.x, bb0.x), 0.f);
    v0.y = fmaxf(fmaf(dv, a0.y, bb0.y), 0.f);
    v0.z = fmaxf(fmaf(dv, a1.x, bb0.z), 0.f);
    v0.w = fmaxf(fmaf(dv, a1.y, bb0.w), 0.f);
    v1.x = fmaxf(fmaf(dv, a2.x, bb1.x), 0.f);
    v1.y = fmaxf(fmaf(dv, a2.y, bb1.y), 0.f);
    v1.z = fmaxf(fmaf(dv, a3.x, bb1.z), 0.f);
    v1.w = fmaxf(fmaf(dv, a3.y, bb1.w), 0.f);
    out4[node * 16 + h * 2]     = v0;
    out4[node * 16 + h * 2 + 1] = v1;

    // self-restoring state for the next launch (initial static values are 0)
    if (gid < N_NODES) g_degi[gid] = 0;
    if (gid < NB_SCAN) { g_flag[gid] = 0; g_agg[gid] = 0; g_inc[gid] = 0; }
}

// ---------------------------------------------------------------------------
// Side stream + events (host objects, static init — no device allocations)
// ---------------------------------------------------------------------------
static cudaStream_t g_s2;
static cudaEvent_t  g_evA, g_evB;
static struct SideStreamInit {
    SideStreamInit() {
        cudaStreamCreateWithFlags(&g_s2, cudaStreamNonBlocking);
        cudaEventCreateWithFlags(&g_evA, cudaEventDisableTiming);
        cudaEventCreateWithFlags(&g_evB, cudaEventDisableTiming);
    }
} g_side_init;

// ---------------------------------------------------------------------------
extern "C" void kernel_launch(void* const* d_in, const int* in_sizes, int n_in,
                              void* d_out, int out_size) {
    const float* features = (const float*)d_in[0];       // [N, 64]
    const void*  edge_idx = d_in[1];                     // [2, E] int32 or int64
    const float* weight   = (const float*)d_in[2];       // [64, 64]
    const float* bias     = (const float*)d_in[3];       // [64]
    float4*      out4     = (float4*)d_out;              // [N, 64] fp32

    const int B = 256;
    cudaStream_t s0 = 0;

    // fork: transform (independent of edges) runs on side stream
    cudaEventRecord(g_evA, s0);
    cudaStreamWaitEvent(g_s2, g_evA, 0);
    k_transform<<<(N_NODES + B - 1) / B, B, 0, g_s2>>>(features, weight);
    cudaEventRecord(g_evB, g_s2);

    // main chain on stream 0
    k_degree_rank<<<(E4 + B - 1) / B, B>>>(edge_idx);
    k_scan<<<NB_SCAN, SCAN_B>>>();

    // join: fill needs rowptr (s0); applydinv needs dinv (s0) + T (s2)
    cudaStreamWaitEvent(s0, g_evB, 0);
    k_fillapply<<<FILLB + APPLYB, B>>>(edge_idx);
    k_gather<<<(N_NODES * 8 + B - 1) / B, B>>>(out4, bias);
}